// round 16
// baseline (speedup 1.0000x reference)
#include <cuda_runtime.h>
#include <cuda_fp16.h>
#include <stdint.h>
#include <math.h>

#define T_TOK 2048
#define HD    2048
#define ID    768
#define NE    64
#define TOPK  8
#define CAPE  512

// ---------------- scratch (device globals) ----------------
__device__ int   g_sel [T_TOK*TOPK];
__device__ float g_wsel[T_TOK*TOPK];
__device__ int   g_tok [NE*CAPE];
__device__ float g_wslot[NE*CAPE];
__device__ int   g_cnt [NE];
__device__ __half g_xh[(size_t)T_TOK*HD];
__device__ __half g_hh[(size_t)NE*CAPE*ID];

// ---------------- helpers ----------------
__device__ __forceinline__ uint32_t s2u(const void* p) {
    uint32_t a;
    asm("{ .reg .u64 t; cvta.to.shared.u64 t, %1; cvt.u32.u64 %0, t; }" : "=r"(a) : "l"(p));
    return a;
}
__device__ __forceinline__ uint32_t sw(uint32_t off) {   // Swizzle<3,4,3> on flat bytes
    return off ^ (((off >> 7) & 7u) << 4);
}
__device__ __forceinline__ void cpa(uint32_t d, const void* s, int nb) {
    asm volatile("cp.async.cg.shared.global [%0], [%1], 16, %2;"
                 :: "r"(d), "l"(s), "r"(nb) : "memory");
}
#define CP_COMMIT() asm volatile("cp.async.commit_group;" ::: "memory")
#define CP_WAIT1()  asm volatile("cp.async.wait_group 1;" ::: "memory")
#define CP_WAIT2()  asm volatile("cp.async.wait_group 2;" ::: "memory")

__device__ __forceinline__ void ldsm4(uint32_t& r0, uint32_t& r1, uint32_t& r2, uint32_t& r3, uint32_t a) {
    asm volatile("ldmatrix.sync.aligned.m8n8.x4.shared.b16 {%0,%1,%2,%3}, [%4];"
                 : "=r"(r0), "=r"(r1), "=r"(r2), "=r"(r3) : "r"(a));
}
__device__ __forceinline__ void ldsm4t(uint32_t& r0, uint32_t& r1, uint32_t& r2, uint32_t& r3, uint32_t a) {
    asm volatile("ldmatrix.sync.aligned.m8n8.x4.trans.shared.b16 {%0,%1,%2,%3}, [%4];"
                 : "=r"(r0), "=r"(r1), "=r"(r2), "=r"(r3) : "r"(a));
}
__device__ __forceinline__ void mma16816(float* c, const uint32_t* a, const uint32_t* b) {
    asm volatile("mma.sync.aligned.m16n8k16.row.col.f32.f16.f16.f32 "
                 "{%0,%1,%2,%3}, {%4,%5,%6,%7}, {%8,%9}, {%0,%1,%2,%3};"
                 : "+f"(c[0]), "+f"(c[1]), "+f"(c[2]), "+f"(c[3])
                 : "r"(a[0]), "r"(a[1]), "r"(a[2]), "r"(a[3]), "r"(b[0]), "r"(b[1]));
}
// 8 fp32 -> 8 fp16 packed as uint4
__device__ __forceinline__ uint4 cvt8(float4 v0, float4 v1) {
    __half2 a = __floats2half2_rn(v0.x, v0.y);
    __half2 b = __floats2half2_rn(v0.z, v0.w);
    __half2 c = __floats2half2_rn(v1.x, v1.y);
    __half2 d = __floats2half2_rn(v1.z, v1.w);
    return make_uint4(*(uint32_t*)&a, *(uint32_t*)&b, *(uint32_t*)&c, *(uint32_t*)&d);
}

// ---------------- prep: convert x, zero y, reset route tables ----------------
__global__ void prep_kernel(const float* __restrict__ src, float* __restrict__ y) {
    const int gi = blockIdx.x*blockDim.x + threadIdx.x;
    const int nthr = gridDim.x*blockDim.x;
    for (int i = gi; i < (T_TOK*HD)/4; i += nthr) {
        float4 v = ((const float4*)src)[i];
        __half2 a = __floats2half2_rn(v.x, v.y);
        __half2 b = __floats2half2_rn(v.z, v.w);
        ((uint2*)g_xh)[i] = make_uint2(*reinterpret_cast<uint32_t*>(&a), *reinterpret_cast<uint32_t*>(&b));
        ((float4*)y)[i] = make_float4(0.f, 0.f, 0.f, 0.f);
    }
    for (int i = gi; i < NE*CAPE; i += nthr) { g_tok[i] = -1; g_wslot[i] = 0.f; }
    if (gi < NE) g_cnt[gi] = 0;
}

// ---------------- gate logits + fused top-8 ----------------
__global__ __launch_bounds__(256) void gate_kernel(const float* __restrict__ x,
                                                   const float* __restrict__ gw) {
    const int t0  = blockIdx.x * 32;
    const int tid = threadIdx.x;
    __shared__ float sx[32][33];
    __shared__ float swt[32][65];
    __shared__ float slog[32][65];
    float acc[8];
    #pragma unroll
    for (int i = 0; i < 8; i++) acc[i] = 0.f;
    const int e  = tid & 63;
    const int tb = tid >> 6;
    for (int k0 = 0; k0 < HD; k0 += 32) {
        #pragma unroll
        for (int j = 0; j < 4; j++) {
            int item = tid + j*256;
            int r = item >> 5, c = item & 31;
            sx[r][c] = x[(size_t)(t0 + r)*HD + k0 + c];
        }
        #pragma unroll
        for (int j = 0; j < 8; j++) {
            int item = tid + j*256;
            int ee = item >> 5, hh = item & 31;
            swt[hh][ee] = gw[(size_t)ee*HD + k0 + hh];
        }
        __syncthreads();
        #pragma unroll
        for (int hh = 0; hh < 32; hh++) {
            float wv = swt[hh][e];
            #pragma unroll
            for (int i = 0; i < 8; i++)
                acc[i] += sx[tb*8 + i][hh] * wv;
        }
        __syncthreads();
    }
    #pragma unroll
    for (int i = 0; i < 8; i++)
        slog[tb*8 + i][e] = acc[i];
    __syncthreads();

    // fused top-8: each warp handles 4 tokens
    const int lane = tid & 31, wid = tid >> 5;
    #pragma unroll 1
    for (int tt = 0; tt < 4; tt++) {
        const int t = wid*4 + tt;
        float v0 = slog[t][lane];
        float v1 = slog[t][lane + 32];
        float vals[8]; int idxs[8];
        #pragma unroll
        for (int r = 0; r < 8; r++) {
            float mv; int mi;
            if (v0 >= v1) { mv = v0; mi = lane; } else { mv = v1; mi = lane + 32; }
            #pragma unroll
            for (int off = 16; off > 0; off >>= 1) {
                float ov = __shfl_down_sync(0xffffffffu, mv, off);
                int   oi = __shfl_down_sync(0xffffffffu, mi, off);
                if (ov > mv || (ov == mv && oi < mi)) { mv = ov; mi = oi; }
            }
            mv = __shfl_sync(0xffffffffu, mv, 0);
            mi = __shfl_sync(0xffffffffu, mi, 0);
            vals[r] = mv; idxs[r] = mi;
            if (mi == lane) v0 = -INFINITY;
            else if (mi == lane + 32) v1 = -INFINITY;
        }
        if (lane == 0) {
            float mx = vals[0];
            float w8[8]; float s8 = 0.f;
            #pragma unroll
            for (int r = 0; r < 8; r++) { w8[r] = expf(vals[r] - mx); s8 += w8[r]; }
            float inv = 1.f / s8;
            #pragma unroll
            for (int r = 0; r < 8; r++) {
                g_sel [(t0 + t)*TOPK + r] = idxs[r];
                g_wsel[(t0 + t)*TOPK + r] = w8[r] * inv;
            }
        }
    }
}

// ---------------- atomic-slot routing ----------------
__global__ void route_kernel() {
    const int i = blockIdx.x*blockDim.x + threadIdx.x;   // 16384 assignments
    const int e = g_sel[i];
    const int pos = atomicAdd(&g_cnt[e], 1);
    if (pos < CAPE) {
        g_tok  [e*CAPE + pos] = i / TOPK;
        g_wslot[e*CAPE + pos] = g_wsel[i];
    }
}

// ================= GEMM1: h = silu(A@Wg)*(A@Wu), fused fp32->fp16 weights =================
// CTA: M=128, N=64. K-chunks of 32. A fp16 4-ring (4x8KB), B fp32 3-ring (3x16KB: G8K+U8K),
// B fp16 2 buffers (2x8KB: G4K+U4K). 2 CTAs/SM.
#define G1_A    0
#define G1_B32  32768
#define G1_B16  (32768 + 49152)
#define G_SMEM  (2048 + 98304)

__global__ __launch_bounds__(256, 2) void gemm1_kernel(const float* __restrict__ wgp,
                                                       const float* __restrict__ wup) {
    const int e  = blockIdx.z;
    const int m0 = blockIdx.y * 128;
    const int n0 = blockIdx.x * 64;
    if (m0 >= g_cnt[e]) return;

    extern __shared__ __align__(1024) char smem_raw[];
    const uint32_t su = s2u(smem_raw);
    const uint32_t tb = (su + 512 + 1023) & ~1023u;
    const uint32_t hb = tb - su;             // byte offset of tb within smem_raw
    int* sTok = (int*)smem_raw;

    const int tid = threadIdx.x;
    if (tid < 128) sTok[tid] = g_tok[e*CAPE + m0 + tid];
    __syncthreads();

    // ---- A staging map (fp16, swizzled) ----
    const int mA  = tid >> 2, kcA = tid & 3;
    const uint32_t dA0 = sw((uint32_t)(mA*64      + kcA*16));
    const uint32_t dA1 = sw((uint32_t)((mA+64)*64 + kcA*16));
    const int tk0 = sTok[mA], tk1 = sTok[mA+64];
    const int nb0 = tk0 >= 0 ? 16 : 0, nb1 = tk1 >= 0 ? 16 : 0;
    const __half* ah0 = g_xh + (size_t)(tk0 >= 0 ? tk0 : 0)*HD + kcA*8;
    const __half* ah1 = g_xh + (size_t)(tk1 >= 0 ? tk1 : 0)*HD + kcA*8;

    // ---- B fp32 staging map: per matrix 32 rows x 64 floats (256B/row) = 512 chunks; 2/thread ----
    const int rB0 = tid >> 4,          cB0 = tid & 15;          // rows 0..15
    const int rB1 = (tid + 256) >> 4,  cB1 = tid & 15;          // rows 16..31
    const uint32_t dB0 = (uint32_t)(rB0*256 + cB0*16);
    const uint32_t dB1 = (uint32_t)(rB1*256 + cB1*16);
    const int NIT = HD / 32;

    auto issue = [&](int it) {
        const int k0 = it * 32;
        const uint32_t sa = tb + G1_A + (uint32_t)(it & 3) * 8192;
        cpa(sa + dA0, ah0 + k0, nb0);
        cpa(sa + dA1, ah1 + k0, nb1);
        const uint32_t sb = tb + G1_B32 + (uint32_t)(it % 3) * 16384;
        const size_t g0 = ((size_t)e*HD + k0 + rB0)*ID + n0 + cB0*4;
        const size_t g1 = ((size_t)e*HD + k0 + rB1)*ID + n0 + cB1*4;
        cpa(sb + dB0,        wgp + g0, 16);
        cpa(sb + dB1,        wgp + g1, 16);
        cpa(sb + 8192 + dB0, wup + g0, 16);
        cpa(sb + 8192 + dB1, wup + g1, 16);
        CP_COMMIT();
    };

    // ---- B conversion map: per matrix 256 8-float chunks = 1/thread ----
    const int rc0 = tid >> 3, cc0 = tid & 7;        // row 0..31, col-chunk 0..7
    const uint32_t so0 = (uint32_t)(rc0*256 + cc0*32);
    const uint32_t do0 = sw((uint32_t)(rc0*128 + cc0*16));

    auto convertB = [&](int it) {
        if (it >= NIT) return;
        const uint32_t sof = hb + G1_B32 + (uint32_t)(it % 3) * 16384;
        const uint32_t dof = hb + G1_B16 + (uint32_t)(it & 1) * 8192;
        float4 v0, v1;
        v0 = *(const float4*)(smem_raw + sof + so0);
        v1 = *(const float4*)(smem_raw + sof + so0 + 16);
        *(uint4*)(smem_raw + dof + do0) = cvt8(v0, v1);
        v0 = *(const float4*)(smem_raw + sof + 8192 + so0);
        v1 = *(const float4*)(smem_raw + sof + 8192 + so0 + 16);
        *(uint4*)(smem_raw + dof + 4096 + do0) = cvt8(v0, v1);
    };

    // ---- compute maps ----
    const int lane = tid & 31, wid = tid >> 5;
    const int wm = wid >> 1, wn = wid & 1;
    uint32_t offA[2][2], offB[2][2];
    #pragma unroll
    for (int tm = 0; tm < 2; tm++)
        #pragma unroll
        for (int ks = 0; ks < 2; ks++)
            offA[tm][ks] = sw((uint32_t)((wm*32 + tm*16 + (lane & 15))*64 + ks*32 + (lane >> 4)*16));
    #pragma unroll
    for (int ks = 0; ks < 2; ks++)
        #pragma unroll
        for (int nh = 0; nh < 2; nh++)
            offB[ks][nh] = sw((uint32_t)((ks*16 + (lane & 15))*128 + wn*64 + nh*32 + (lane >> 4)*16));

    float cG[2][4][4], cU[2][4][4];
    #pragma unroll
    for (int a = 0; a < 2; a++)
        #pragma unroll
        for (int b = 0; b < 4; b++)
            #pragma unroll
            for (int c = 0; c < 4; c++) { cG[a][b][c] = 0.f; cU[a][b][c] = 0.f; }

    issue(0); issue(1); issue(2);
    CP_WAIT2();
    __syncthreads();
    convertB(0);

    #pragma unroll 1
    for (int it = 0; it < NIT; it++) {
        CP_WAIT1();
        __syncthreads();
        convertB(it + 1);
        if (it + 3 < NIT) issue(it + 3);
        else CP_COMMIT();
        const uint32_t sa = tb + G1_A + (uint32_t)(it & 3) * 8192;
        const uint32_t bb = tb + G1_B16 + (uint32_t)(it & 1) * 8192;
        #pragma unroll
        for (int ks = 0; ks < 2; ks++) {
            uint32_t aH[2][4];
            #pragma unroll
            for (int tm = 0; tm < 2; tm++)
                ldsm4(aH[tm][0], aH[tm][1], aH[tm][2], aH[tm][3], sa + offA[tm][ks]);
            uint32_t bg[4][2], bu[4][2];
            #pragma unroll
            for (int nh = 0; nh < 2; nh++) {
                ldsm4t(bg[nh*2][0], bg[nh*2][1], bg[nh*2+1][0], bg[nh*2+1][1], bb + offB[ks][nh]);
                ldsm4t(bu[nh*2][0], bu[nh*2][1], bu[nh*2+1][0], bu[nh*2+1][1], bb + 4096 + offB[ks][nh]);
            }
            #pragma unroll
            for (int tm = 0; tm < 2; tm++)
                #pragma unroll
                for (int tn = 0; tn < 4; tn++) {
                    mma16816(cG[tm][tn], aH[tm], bg[tn]);
                    mma16816(cU[tm][tn], aH[tm], bu[tn]);
                }
        }
    }

    // ---- epilogue: silu(G)*U -> smem tile (stride 72 halves) -> coalesced 16B stores ----
    __syncthreads();
    const int r4 = lane >> 2, cp2 = (lane & 3) * 2;
    #pragma unroll
    for (int tm = 0; tm < 2; tm++)
        #pragma unroll
        for (int tn = 0; tn < 4; tn++) {
            const int rloc0 = wm*32 + tm*16 + r4;
            const int col   = wn*32 + tn*8 + cp2;
            #pragma unroll
            for (int half = 0; half < 2; half++) {
                float g0 = cG[tm][tn][half*2],     u0 = cU[tm][tn][half*2];
                float g1 = cG[tm][tn][half*2 + 1], u1 = cU[tm][tn][half*2 + 1];
                float h0 = g0 / (1.f + __expf(-g0)) * u0;
                float h1 = g1 / (1.f + __expf(-g1)) * u1;
                __half2 hh = __floats2half2_rn(h0, h1);
                *(uint32_t*)(smem_raw + hb + (uint32_t)((rloc0 + half*8)*144 + col*2)) =
                    *reinterpret_cast<uint32_t*>(&hh);
            }
        }
    __syncthreads();
    #pragma unroll
    for (int j = 0; j < 4; j++) {
        const int idx = tid + j*256;           // 1024 chunks of 8 cols
        const int row = idx >> 3, c8 = idx & 7;
        uint4 v = *(const uint4*)(smem_raw + hb + (uint32_t)(row*144 + c8*16));
        *(uint4*)(g_hh + ((size_t)e*CAPE + m0 + row)*ID + n0 + c8*8) = v;
    }
}

// ================= GEMM2: y += w * (h @ wd), fused fp32->fp16 weights =================
// CTA: M=128, N=128. A fp16 4-ring (4x8KB), B fp32 3-ring (3x16KB: 32x128 fp32),
// B fp16 2 buffers (2x8KB: 2 slabs x 4KB). 2 CTAs/SM.
#define G2_A    0
#define G2_B32  32768
#define G2_B16  (32768 + 49152)

__global__ __launch_bounds__(256, 2) void gemm2_kernel(const float* __restrict__ wdp,
                                                       float* __restrict__ y) {
    const int e  = blockIdx.z;
    const int m0 = blockIdx.y * 128;
    const int n0 = blockIdx.x * 128;
    if (m0 >= g_cnt[e]) return;

    extern __shared__ __align__(1024) char smem_raw[];
    const uint32_t su = s2u(smem_raw);
    const uint32_t tb = (su + 1024 + 1023) & ~1023u;
    const uint32_t hb = tb - su;
    int*   sTok = (int*)smem_raw;
    float* sW   = (float*)(smem_raw + 512);
    const int tid = threadIdx.x;
    if (tid < 128) {
        sTok[tid] = g_tok  [e*CAPE + m0 + tid];
        sW[tid]   = g_wslot[e*CAPE + m0 + tid];
    }
    __syncthreads();

    const int mA = tid >> 2, kcA = tid & 3;
    const uint32_t dA0 = sw((uint32_t)(mA*64      + kcA*16));
    const uint32_t dA1 = sw((uint32_t)((mA+64)*64 + kcA*16));

    // B fp32 staging: 32 rows x 128 floats (512B/row) = 1024 16B chunks, 4/thread
    uint32_t dB[4]; int rB[4], cB[4];
    #pragma unroll
    for (int j = 0; j < 4; j++) {
        int c = tid + j*256;
        rB[j] = c >> 5; cB[j] = c & 31;
        dB[j] = (uint32_t)(rB[j]*512 + cB[j]*16);
    }
    const int NIT = ID / 32;

    auto issue = [&](int it) {
        const int k0 = it * 32;
        const uint32_t sa = tb + G2_A + (uint32_t)(it & 3) * 8192;
        const size_t ga0 = ((size_t)e*CAPE + m0 + mA)*ID + k0 + kcA*8;
        const size_t ga1 = ((size_t)e*CAPE + m0 + mA + 64)*ID + k0 + kcA*8;
        cpa(sa + dA0, g_hh + ga0, 16);
        cpa(sa + dA1, g_hh + ga1, 16);
        const uint32_t sb = tb + G2_B32 + (uint32_t)(it % 3) * 16384;
        #pragma unroll
        for (int j = 0; j < 4; j++) {
            const size_t gb = ((size_t)e*ID + k0 + rB[j])*HD + n0 + cB[j]*4;
            cpa(sb + dB[j], wdp + gb, 16);
        }
        CP_COMMIT();
    };

    // conversion: 512 8-float chunks (32 rows x 16 col8), 2/thread
    uint32_t so[2], dof[2];
    #pragma unroll
    for (int j = 0; j < 2; j++) {
        int c = tid + j*256;
        int row = c >> 4, col8 = c & 15;
        so[j]  = (uint32_t)(row*512 + col8*32);
        dof[j] = (uint32_t)((col8 >> 3)*4096) + sw((uint32_t)(row*128 + (col8 & 7)*16));
    }
    auto convertB = [&](int it) {
        if (it >= NIT) return;
        const uint32_t sof = hb + G2_B32 + (uint32_t)(it % 3) * 16384;
        const uint32_t dB16 = hb + G2_B16 + (uint32_t)(it & 1) * 8192;
        #pragma unroll
        for (int j = 0; j < 2; j++) {
            float4 v0 = *(const float4*)(smem_raw + sof + so[j]);
            float4 v1 = *(const float4*)(smem_raw + sof + so[j] + 16);
            *(uint4*)(smem_raw + dB16 + dof[j]) = cvt8(v0, v1);
        }
    };

    const int lane = tid & 31, wid = tid >> 5;
    const int wm = wid >> 1, wn = wid & 1;   // warp tile 32 rows x 64 cols
    uint32_t offA[2][2], offB[2][4];
    #pragma unroll
    for (int tm = 0; tm < 2; tm++)
        #pragma unroll
        for (int ks = 0; ks < 2; ks++)
            offA[tm][ks] = sw((uint32_t)((wm*32 + tm*16 + (lane & 15))*64 + ks*32 + (lane >> 4)*16));
    #pragma unroll
    for (int ks = 0; ks < 2; ks++)
        #pragma unroll
        for (int nh = 0; nh < 4; nh++)
            offB[ks][nh] = (uint32_t)(wn*4096) +
                           sw((uint32_t)((ks*16 + (lane & 15))*128 + nh*32 + (lane >> 4)*16));

    float cc[2][8][4];
    #pragma unroll
    for (int a = 0; a < 2; a++)
        #pragma unroll
        for (int b = 0; b < 8; b++)
            #pragma unroll
            for (int c = 0; c < 4; c++) cc[a][b][c] = 0.f;

    issue(0); issue(1); issue(2);
    CP_WAIT2();
    __syncthreads();
    convertB(0);

    #pragma unroll 1
    for (int it = 0; it < NIT; it++) {
        CP_WAIT1();
        __syncthreads();
        convertB(it + 1);
        if (it + 3 < NIT) issue(it + 3);
        else CP_COMMIT();
        const uint32_t sa = tb + G2_A + (uint32_t)(it & 3) * 8192;
        const uint32_t bb = tb + G2_B16 + (uint32_t)(it & 1) * 8192;
        #pragma unroll
        for (int ks = 0; ks < 2; ks++) {
            uint32_t aH[2][4];
            #pragma unroll
            for (int tm = 0; tm < 2; tm++)
                ldsm4(aH[tm][0], aH[tm][1], aH[tm][2], aH[tm][3], sa + offA[tm][ks]);
            uint32_t bh[8][2];
            #pragma unroll
            for (int nh = 0; nh < 4; nh++)
                ldsm4t(bh[nh*2][0], bh[nh*2][1], bh[nh*2+1][0], bh[nh*2+1][1], bb + offB[ks][nh]);
            #pragma unroll
            for (int tm = 0; tm < 2; tm++)
                #pragma unroll
                for (int tn = 0; tn < 8; tn++)
                    mma16816(cc[tm][tn], aH[tm], bh[tn]);
        }
    }

    // epilogue: scatter-add w * out into y
    const int r4 = lane >> 2, cp2 = (lane & 3) * 2;
    #pragma unroll
    for (int tm = 0; tm < 2; tm++)
        #pragma unroll
        for (int half = 0; half < 2; half++) {
            const int rloc = wm*32 + tm*16 + r4 + half*8;
            const int tok = sTok[rloc];
            if (tok < 0) continue;
            const float w = sW[rloc];
            float* yrow = y + (size_t)tok*HD;
            #pragma unroll
            for (int tn = 0; tn < 8; tn++) {
                const int col = n0 + wn*64 + tn*8 + cp2;
                atomicAdd(yrow + col,     w * cc[tm][tn][half*2]);
                atomicAdd(yrow + col + 1, w * cc[tm][tn][half*2 + 1]);
            }
        }
}

// ---------------- launch ----------------
extern "C" void kernel_launch(void* const* d_in, const int* in_sizes, int n_in,
                              void* d_out, int out_size) {
    const float* x      = (const float*)d_in[0];
    const float* gate_w = (const float*)d_in[1];
    const float* wg     = (const float*)d_in[2];
    const float* wu     = (const float*)d_in[3];
    const float* wd     = (const float*)d_in[4];
    float* y = (float*)d_out;

    cudaFuncSetAttribute(gemm1_kernel, cudaFuncAttributeMaxDynamicSharedMemorySize, G_SMEM);
    cudaFuncSetAttribute(gemm2_kernel, cudaFuncAttributeMaxDynamicSharedMemorySize, G_SMEM);

    prep_kernel<<<1024, 256>>>(x, y);
    gate_kernel<<<T_TOK/32, 256>>>(x, gate_w);
    route_kernel<<<(T_TOK*TOPK)/256, 256>>>();

    gemm1_kernel<<<dim3(ID/64,  CAPE/128, NE), 256, G_SMEM>>>(wg, wu);
    gemm2_kernel<<<dim3(HD/128, CAPE/128, NE), 256, G_SMEM>>>(wd, y);
}

// round 17
// speedup vs baseline: 1.0417x; 1.0417x over previous
#include <cuda_runtime.h>
#include <cuda_fp16.h>
#include <stdint.h>
#include <math.h>

#define T_TOK 2048
#define HD    2048
#define ID    768
#define NE    64
#define TOPK  8
#define CAPE  512

// ---------------- scratch (device globals) ----------------
__device__ int   g_sel [T_TOK*TOPK];
__device__ float g_wsel[T_TOK*TOPK];
__device__ int   g_tok [NE*CAPE];
__device__ float g_wslot[NE*CAPE];
__device__ int   g_cnt [NE];
__device__ __half g_xh[(size_t)T_TOK*HD];
__device__ __half g_hh[(size_t)NE*CAPE*ID];

// ---------------- helpers ----------------
__device__ __forceinline__ uint32_t s2u(const void* p) {
    uint32_t a;
    asm("{ .reg .u64 t; cvta.to.shared.u64 t, %1; cvt.u32.u64 %0, t; }" : "=r"(a) : "l"(p));
    return a;
}
__device__ __forceinline__ uint32_t sw(uint32_t off) {   // Swizzle<3,4,3> on flat bytes
    return off ^ (((off >> 7) & 7u) << 4);
}
__device__ __forceinline__ void cpa(uint32_t d, const void* s, int nb) {
    asm volatile("cp.async.cg.shared.global [%0], [%1], 16, %2;"
                 :: "r"(d), "l"(s), "r"(nb) : "memory");
}
#define CP_COMMIT() asm volatile("cp.async.commit_group;" ::: "memory")
#define CP_WAIT1()  asm volatile("cp.async.wait_group 1;" ::: "memory")

__device__ __forceinline__ void ldsm4(uint32_t& r0, uint32_t& r1, uint32_t& r2, uint32_t& r3, uint32_t a) {
    asm volatile("ldmatrix.sync.aligned.m8n8.x4.shared.b16 {%0,%1,%2,%3}, [%4];"
                 : "=r"(r0), "=r"(r1), "=r"(r2), "=r"(r3) : "r"(a));
}
__device__ __forceinline__ void ldsm4t(uint32_t& r0, uint32_t& r1, uint32_t& r2, uint32_t& r3, uint32_t a) {
    asm volatile("ldmatrix.sync.aligned.m8n8.x4.trans.shared.b16 {%0,%1,%2,%3}, [%4];"
                 : "=r"(r0), "=r"(r1), "=r"(r2), "=r"(r3) : "r"(a));
}
__device__ __forceinline__ void mma16816(float* c, const uint32_t* a, const uint32_t* b) {
    asm volatile("mma.sync.aligned.m16n8k16.row.col.f32.f16.f16.f32 "
                 "{%0,%1,%2,%3}, {%4,%5,%6,%7}, {%8,%9}, {%0,%1,%2,%3};"
                 : "+f"(c[0]), "+f"(c[1]), "+f"(c[2]), "+f"(c[3])
                 : "r"(a[0]), "r"(a[1]), "r"(a[2]), "r"(a[3]), "r"(b[0]), "r"(b[1]));
}
// 8 fp32 -> 8 fp16 packed as uint4
__device__ __forceinline__ uint4 cvt8(float4 v0, float4 v1) {
    __half2 a = __floats2half2_rn(v0.x, v0.y);
    __half2 b = __floats2half2_rn(v0.z, v0.w);
    __half2 c = __floats2half2_rn(v1.x, v1.y);
    __half2 d = __floats2half2_rn(v1.z, v1.w);
    return make_uint4(*(uint32_t*)&a, *(uint32_t*)&b, *(uint32_t*)&c, *(uint32_t*)&d);
}

// ---------------- prep: convert x, zero y, reset route tables ----------------
__global__ void prep_kernel(const float* __restrict__ src, float* __restrict__ y) {
    const int gi = blockIdx.x*blockDim.x + threadIdx.x;
    const int nthr = gridDim.x*blockDim.x;
    for (int i = gi; i < (T_TOK*HD)/4; i += nthr) {
        float4 v = ((const float4*)src)[i];
        __half2 a = __floats2half2_rn(v.x, v.y);
        __half2 b = __floats2half2_rn(v.z, v.w);
        ((uint2*)g_xh)[i] = make_uint2(*reinterpret_cast<uint32_t*>(&a), *reinterpret_cast<uint32_t*>(&b));
        ((float4*)y)[i] = make_float4(0.f, 0.f, 0.f, 0.f);
    }
    for (int i = gi; i < NE*CAPE; i += nthr) { g_tok[i] = -1; g_wslot[i] = 0.f; }
    if (gi < NE) g_cnt[gi] = 0;
}

// ---------------- gate logits + fused top-8 ----------------
__global__ __launch_bounds__(256) void gate_kernel(const float* __restrict__ x,
                                                   const float* __restrict__ gw) {
    const int t0  = blockIdx.x * 32;
    const int tid = threadIdx.x;
    __shared__ float sx[32][33];
    __shared__ float swt[32][65];
    __shared__ float slog[32][65];
    float acc[8];
    #pragma unroll
    for (int i = 0; i < 8; i++) acc[i] = 0.f;
    const int e  = tid & 63;
    const int tb = tid >> 6;
    for (int k0 = 0; k0 < HD; k0 += 32) {
        #pragma unroll
        for (int j = 0; j < 4; j++) {
            int item = tid + j*256;
            int r = item >> 5, c = item & 31;
            sx[r][c] = x[(size_t)(t0 + r)*HD + k0 + c];
        }
        #pragma unroll
        for (int j = 0; j < 8; j++) {
            int item = tid + j*256;
            int ee = item >> 5, hh = item & 31;
            swt[hh][ee] = gw[(size_t)ee*HD + k0 + hh];
        }
        __syncthreads();
        #pragma unroll
        for (int hh = 0; hh < 32; hh++) {
            float wv = swt[hh][e];
            #pragma unroll
            for (int i = 0; i < 8; i++)
                acc[i] += sx[tb*8 + i][hh] * wv;
        }
        __syncthreads();
    }
    #pragma unroll
    for (int i = 0; i < 8; i++)
        slog[tb*8 + i][e] = acc[i];
    __syncthreads();

    const int lane = tid & 31, wid = tid >> 5;
    #pragma unroll 1
    for (int tt = 0; tt < 4; tt++) {
        const int t = wid*4 + tt;
        float v0 = slog[t][lane];
        float v1 = slog[t][lane + 32];
        float vals[8]; int idxs[8];
        #pragma unroll
        for (int r = 0; r < 8; r++) {
            float mv; int mi;
            if (v0 >= v1) { mv = v0; mi = lane; } else { mv = v1; mi = lane + 32; }
            #pragma unroll
            for (int off = 16; off > 0; off >>= 1) {
                float ov = __shfl_down_sync(0xffffffffu, mv, off);
                int   oi = __shfl_down_sync(0xffffffffu, mi, off);
                if (ov > mv || (ov == mv && oi < mi)) { mv = ov; mi = oi; }
            }
            mv = __shfl_sync(0xffffffffu, mv, 0);
            mi = __shfl_sync(0xffffffffu, mi, 0);
            vals[r] = mv; idxs[r] = mi;
            if (mi == lane) v0 = -INFINITY;
            else if (mi == lane + 32) v1 = -INFINITY;
        }
        if (lane == 0) {
            float mx = vals[0];
            float w8[8]; float s8 = 0.f;
            #pragma unroll
            for (int r = 0; r < 8; r++) { w8[r] = expf(vals[r] - mx); s8 += w8[r]; }
            float inv = 1.f / s8;
            #pragma unroll
            for (int r = 0; r < 8; r++) {
                g_sel [(t0 + t)*TOPK + r] = idxs[r];
                g_wsel[(t0 + t)*TOPK + r] = w8[r] * inv;
            }
        }
    }
}

// ---------------- atomic-slot routing ----------------
__global__ void route_kernel() {
    const int i = blockIdx.x*blockDim.x + threadIdx.x;
    const int e = g_sel[i];
    const int pos = atomicAdd(&g_cnt[e], 1);
    if (pos < CAPE) {
        g_tok  [e*CAPE + pos] = i / TOPK;
        g_wslot[e*CAPE + pos] = g_wsel[i];
    }
}

// ================= GEMM1: h = silu(A@Wg)*(A@Wu), register-converted weights =================
// CTA: M=128, N=64. K=32 chunks. A fp16 4-ring (4x8KB) via cp.async.
// B: LDG fp32 -> cvt -> STS fp16 into 2x8KB double buffer (G4K+U4K). 2 CTAs/SM.
#define G1_A    0
#define G1_B16  32768
#define G_SMEM  (2048 + 49152)

__global__ __launch_bounds__(256, 2) void gemm1_kernel(const float* __restrict__ wgp,
                                                       const float* __restrict__ wup) {
    const int e  = blockIdx.z;
    const int m0 = blockIdx.y * 128;
    const int n0 = blockIdx.x * 64;
    if (m0 >= g_cnt[e]) return;

    extern __shared__ __align__(1024) char smem_raw[];
    const uint32_t su = s2u(smem_raw);
    const uint32_t tb = (su + 512 + 1023) & ~1023u;
    int* sTok = (int*)smem_raw;

    const int tid = threadIdx.x;
    if (tid < 128) sTok[tid] = g_tok[e*CAPE + m0 + tid];
    __syncthreads();

    // ---- A staging (cp.async fp16, swizzled) ----
    const int mA  = tid >> 2, kcA = tid & 3;
    const uint32_t dA0 = sw((uint32_t)(mA*64      + kcA*16));
    const uint32_t dA1 = sw((uint32_t)((mA+64)*64 + kcA*16));
    const int tk0 = sTok[mA], tk1 = sTok[mA+64];
    const int nb0 = tk0 >= 0 ? 16 : 0, nb1 = tk1 >= 0 ? 16 : 0;
    const __half* ah0 = g_xh + (size_t)(tk0 >= 0 ? tk0 : 0)*HD + kcA*8;
    const __half* ah1 = g_xh + (size_t)(tk1 >= 0 ? tk1 : 0)*HD + kcA*8;
    const int NIT = HD / 32;

    auto issueA = [&](int it) {
        const int k0 = it * 32;
        const uint32_t sa = tb + G1_A + (uint32_t)(it & 3) * 8192;
        cpa(sa + dA0, ah0 + k0, nb0);
        cpa(sa + dA1, ah1 + k0, nb1);
        CP_COMMIT();
    };

    // ---- B: LDG fp32 (8 floats/thread/matrix) -> cvt -> STS ----
    const int rcB = tid >> 3, ccB = tid & 7;        // row 0..31, 8-float group 0..7
    const uint32_t doB = sw((uint32_t)(rcB*128 + ccB*16));
    const float* gbase = (const float*)nullptr;
    const size_t bOff = ((size_t)e*HD + rcB)*ID + n0 + ccB*8;
    float4 pg0, pg1, pu0, pu1;

    auto ldgB = [&](int it) {
        if (it >= NIT) return;
        const float* pg = wgp + bOff + (size_t)it*32*ID;
        const float* pu = wup + bOff + (size_t)it*32*ID;
        pg0 = ((const float4*)pg)[0]; pg1 = ((const float4*)pg)[1];
        pu0 = ((const float4*)pu)[0]; pu1 = ((const float4*)pu)[1];
    };
    auto stsB = [&](int it) {
        if (it >= NIT) return;
        const uint32_t dof = tb - su + G1_B16 + (uint32_t)(it & 1) * 8192;
        *(uint4*)(smem_raw + dof + doB)        = cvt8(pg0, pg1);
        *(uint4*)(smem_raw + dof + 4096 + doB) = cvt8(pu0, pu1);
    };
    (void)gbase;

    // ---- compute maps ----
    const int lane = tid & 31, wid = tid >> 5;
    const int wm = wid >> 1, wn = wid & 1;
    uint32_t offA[2][2];
    #pragma unroll
    for (int tm = 0; tm < 2; tm++)
        #pragma unroll
        for (int ks = 0; ks < 2; ks++)
            offA[tm][ks] = sw((uint32_t)((wm*32 + tm*16 + (lane & 15))*64 + ks*32 + (lane >> 4)*16));

    float cG[2][4][4], cU[2][4][4];
    #pragma unroll
    for (int a = 0; a < 2; a++)
        #pragma unroll
        for (int b = 0; b < 4; b++)
            #pragma unroll
            for (int c = 0; c < 4; c++) { cG[a][b][c] = 0.f; cU[a][b][c] = 0.f; }

    // prologue
    ldgB(0);
    issueA(0); issueA(1); issueA(2);
    stsB(0);
    ldgB(1);

    #pragma unroll 1
    for (int it = 0; it < NIT; it++) {
        CP_WAIT1();
        __syncthreads();
        stsB(it + 1);          // from regs loaded last iter; writes slot (it+1)&1
        ldgB(it + 2);          // prefetch next
        if (it + 3 < NIT) issueA(it + 3);
        else CP_COMMIT();
        const uint32_t sa = tb + G1_A + (uint32_t)(it & 3) * 8192;
        const uint32_t bb = tb + G1_B16 + (uint32_t)(it & 1) * 8192;
        #pragma unroll
        for (int ks = 0; ks < 2; ks++) {
            uint32_t aH[2][4];
            #pragma unroll
            for (int tm = 0; tm < 2; tm++)
                ldsm4(aH[tm][0], aH[tm][1], aH[tm][2], aH[tm][3], sa + offA[tm][ks]);
            uint32_t bg[4][2], bu[4][2];
            #pragma unroll
            for (int nh = 0; nh < 2; nh++) {
                const uint32_t ob = sw((uint32_t)((ks*16 + (lane & 15))*128 + wn*64 + nh*32 + (lane >> 4)*16));
                ldsm4t(bg[nh*2][0], bg[nh*2][1], bg[nh*2+1][0], bg[nh*2+1][1], bb + ob);
                ldsm4t(bu[nh*2][0], bu[nh*2][1], bu[nh*2+1][0], bu[nh*2+1][1], bb + 4096 + ob);
            }
            #pragma unroll
            for (int tm = 0; tm < 2; tm++)
                #pragma unroll
                for (int tn = 0; tn < 4; tn++) {
                    mma16816(cG[tm][tn], aH[tm], bg[tn]);
                    mma16816(cU[tm][tn], aH[tm], bu[tn]);
                }
        }
    }

    // epilogue: h = silu(G)*U -> fp16
    const int r4 = lane >> 2, cp2 = (lane & 3) * 2;
    #pragma unroll
    for (int tm = 0; tm < 2; tm++)
        #pragma unroll
        for (int tn = 0; tn < 4; tn++) {
            const int row0 = m0 + wm*32 + tm*16 + r4;
            const int col  = n0 + wn*32 + tn*8 + cp2;
            #pragma unroll
            for (int half = 0; half < 2; half++) {
                float g0 = cG[tm][tn][half*2],     u0 = cU[tm][tn][half*2];
                float g1 = cG[tm][tn][half*2 + 1], u1 = cU[tm][tn][half*2 + 1];
                float h0 = g0 / (1.f + __expf(-g0)) * u0;
                float h1 = g1 / (1.f + __expf(-g1)) * u1;
                __half2 hh = __floats2half2_rn(h0, h1);
                const size_t o = ((size_t)e*CAPE + row0 + half*8)*ID + col;
                *(uint32_t*)(g_hh + o) = *reinterpret_cast<uint32_t*>(&hh);
            }
        }
}

// ================= GEMM2: y += w * (h @ wd), register-converted weights =================
// CTA: M=128, N=128. A fp16 4-ring (4x8KB). B: LDG fp32 -> cvt -> STS fp16
// into 2x8KB double buffer (2 slabs x 4KB). 2 CTAs/SM.
#define G2_A    0
#define G2_B16  32768

__global__ __launch_bounds__(256, 2) void gemm2_kernel(const float* __restrict__ wdp,
                                                       float* __restrict__ y) {
    const int e  = blockIdx.z;
    const int m0 = blockIdx.y * 128;
    const int n0 = blockIdx.x * 128;
    if (m0 >= g_cnt[e]) return;

    extern __shared__ __align__(1024) char smem_raw[];
    const uint32_t su = s2u(smem_raw);
    const uint32_t tb = (su + 1024 + 1023) & ~1023u;
    int*   sTok = (int*)smem_raw;
    float* sW   = (float*)(smem_raw + 512);
    const int tid = threadIdx.x;
    if (tid < 128) {
        sTok[tid] = g_tok  [e*CAPE + m0 + tid];
        sW[tid]   = g_wslot[e*CAPE + m0 + tid];
    }
    __syncthreads();

    const int mA = tid >> 2, kcA = tid & 3;
    const uint32_t dA0 = sw((uint32_t)(mA*64      + kcA*16));
    const uint32_t dA1 = sw((uint32_t)((mA+64)*64 + kcA*16));
    const int NIT = ID / 32;

    auto issueA = [&](int it) {
        const int k0 = it * 32;
        const uint32_t sa = tb + G2_A + (uint32_t)(it & 3) * 8192;
        const size_t ga0 = ((size_t)e*CAPE + m0 + mA)*ID + k0 + kcA*8;
        const size_t ga1 = ((size_t)e*CAPE + m0 + mA + 64)*ID + k0 + kcA*8;
        cpa(sa + dA0, g_hh + ga0, 16);
        cpa(sa + dA1, g_hh + ga1, 16);
        CP_COMMIT();
    };

    // B: 32 rows x 128 cols fp32 = 512 8-float groups; 2/thread
    // group g = tid + j*256: row = g>>4, cc = g&15
    const int rB0 = tid >> 4,          cc0 = tid & 15;
    const int rB1 = (tid + 256) >> 4,  cc1 = tid & 15;
    const uint32_t doB0 = (uint32_t)((cc0 >> 3)*4096) + sw((uint32_t)(rB0*128 + (cc0 & 7)*16));
    const uint32_t doB1 = (uint32_t)((cc1 >> 3)*4096) + sw((uint32_t)(rB1*128 + (cc1 & 7)*16));
    const size_t bOff0 = ((size_t)e*ID + rB0)*HD + n0 + cc0*8;
    const size_t bOff1 = ((size_t)e*ID + rB1)*HD + n0 + cc1*8;
    float4 pb00, pb01, pb10, pb11;

    auto ldgB = [&](int it) {
        if (it >= NIT) return;
        const float* p0 = wdp + bOff0 + (size_t)it*32*HD;
        const float* p1 = wdp + bOff1 + (size_t)it*32*HD;
        pb00 = ((const float4*)p0)[0]; pb01 = ((const float4*)p0)[1];
        pb10 = ((const float4*)p1)[0]; pb11 = ((const float4*)p1)[1];
    };
    auto stsB = [&](int it) {
        if (it >= NIT) return;
        const uint32_t dof = tb - su + G2_B16 + (uint32_t)(it & 1) * 8192;
        *(uint4*)(smem_raw + dof + doB0) = cvt8(pb00, pb01);
        *(uint4*)(smem_raw + dof + doB1) = cvt8(pb10, pb11);
    };

    const int lane = tid & 31, wid = tid >> 5;
    const int wm = wid >> 1, wn = wid & 1;   // warp tile 32 rows x 64 cols
    uint32_t offA[2][2];
    #pragma unroll
    for (int tm = 0; tm < 2; tm++)
        #pragma unroll
        for (int ks = 0; ks < 2; ks++)
            offA[tm][ks] = sw((uint32_t)((wm*32 + tm*16 + (lane & 15))*64 + ks*32 + (lane >> 4)*16));

    float cc[2][8][4];
    #pragma unroll
    for (int a = 0; a < 2; a++)
        #pragma unroll
        for (int b = 0; b < 8; b++)
            #pragma unroll
            for (int c = 0; c < 4; c++) cc[a][b][c] = 0.f;

    ldgB(0);
    issueA(0); issueA(1); issueA(2);
    stsB(0);
    ldgB(1);

    #pragma unroll 1
    for (int it = 0; it < NIT; it++) {
        CP_WAIT1();
        __syncthreads();
        stsB(it + 1);
        ldgB(it + 2);
        if (it + 3 < NIT) issueA(it + 3);
        else CP_COMMIT();
        const uint32_t sa = tb + G2_A + (uint32_t)(it & 3) * 8192;
        const uint32_t bb = tb + G2_B16 + (uint32_t)(it & 1) * 8192;
        #pragma unroll
        for (int ks = 0; ks < 2; ks++) {
            uint32_t aH[2][4];
            #pragma unroll
            for (int tm = 0; tm < 2; tm++)
                ldsm4(aH[tm][0], aH[tm][1], aH[tm][2], aH[tm][3], sa + offA[tm][ks]);
            uint32_t bh[8][2];
            #pragma unroll
            for (int nh = 0; nh < 4; nh++) {
                const uint32_t ob = (uint32_t)(wn*4096) +
                    sw((uint32_t)((ks*16 + (lane & 15))*128 + nh*32 + (lane >> 4)*16));
                ldsm4t(bh[nh*2][0], bh[nh*2][1], bh[nh*2+1][0], bh[nh*2+1][1], bb + ob);
            }
            #pragma unroll
            for (int tm = 0; tm < 2; tm++)
                #pragma unroll
                for (int tn = 0; tn < 8; tn++)
                    mma16816(cc[tm][tn], aH[tm], bh[tn]);
        }
    }

    // epilogue: scatter-add w * out into y
    const int r4 = lane >> 2, cp2 = (lane & 3) * 2;
    #pragma unroll
    for (int tm = 0; tm < 2; tm++)
        #pragma unroll
        for (int half = 0; half < 2; half++) {
            const int rloc = wm*32 + tm*16 + r4 + half*8;
            const int tok = sTok[rloc];
            if (tok < 0) continue;
            const float w = sW[rloc];
            float* yrow = y + (size_t)tok*HD;
            #pragma unroll
            for (int tn = 0; tn < 8; tn++) {
                const int col = n0 + wn*64 + tn*8 + cp2;
                atomicAdd(yrow + col,     w * cc[tm][tn][half*2]);
                atomicAdd(yrow + col + 1, w * cc[tm][tn][half*2 + 1]);
            }
        }
}

// ---------------- launch ----------------
extern "C" void kernel_launch(void* const* d_in, const int* in_sizes, int n_in,
                              void* d_out, int out_size) {
    const float* x      = (const float*)d_in[0];
    const float* gate_w = (const float*)d_in[1];
    const float* wg     = (const float*)d_in[2];
    const float* wu     = (const float*)d_in[3];
    const float* wd     = (const float*)d_in[4];
    float* y = (float*)d_out;

    cudaFuncSetAttribute(gemm1_kernel, cudaFuncAttributeMaxDynamicSharedMemorySize, G_SMEM);
    cudaFuncSetAttribute(gemm2_kernel, cudaFuncAttributeMaxDynamicSharedMemorySize, G_SMEM);

    prep_kernel<<<1024, 256>>>(x, y);
    gate_kernel<<<T_TOK/32, 256>>>(x, gate_w);
    route_kernel<<<(T_TOK*TOPK)/256, 256>>>();

    gemm1_kernel<<<dim3(ID/64,  CAPE/128, NE), 256, G_SMEM>>>(wg, wu);
    gemm2_kernel<<<dim3(HD/128, CAPE/128, NE), 256, G_SMEM>>>(wd, y);
}